// round 14
// baseline (speedup 1.0000x reference)
#include <cuda_runtime.h>
#include <cstdint>

#define THREADS 256
#define ROWS    256   // rows per block
#define NDIM    6
#define JLEV    8
#define CHAN    64

// ---------------------------------------------------------------------------
// CONVERGED (R9 config): LTS-capped kernel at the chip-wide L2 ceiling
// (~6300 B/cyc path-independent). Per-launch L2 traffic is compulsory:
//   512MB codebook L2-hit reads + 512MB output writes + ~70MB misc = 1.09GB
//   -> 1.09GB / 6300 B/cyc @ ~1.9GHz NAT ~= 91us. Measured 91.1us (ncu).
// Verified experimentally: occupancy (regs=40 -> 6 blocks/SM) is necessary;
// every variant that raised reg pressure (persistence, double-buffer,
// shuffle-index, ROWS=512) regressed. Dataflow:
//  phase 1: stage z chunk in SMEM (float4-coalesced), compute packed
//           big_index branchlessly (sorted edges -> popcount of v>=p[j]),
//           pre-scale gather offsets into SMEM.
//  phase 2: cooperative codebook gather, 16 lanes x float4 per row, MLP-4
//           batches, 256B fully-coalesced rows; __ldcg (skip useless L1),
//           __stcs (keep 512MB stream from evicting L2-resident codebook).
// ---------------------------------------------------------------------------
__global__ __launch_bounds__(THREADS)
void fsq_quantize_kernel(const float* __restrict__ z,
                         const float* __restrict__ perc,
                         const float* __restrict__ cb,
                         float* __restrict__ out_q,      // [B,64]
                         float* __restrict__ out_idx_f,  // [B] float tail
                         int B)
{
    __shared__ float sz[ROWS * NDIM];     // 6 KB
    __shared__ float sp[JLEV * NDIM];     // 192 B
    __shared__ long long soff[ROWS];      // 2 KB: precomputed float-offsets

    const int tid = threadIdx.x;
    const long long base = (long long)blockIdx.x * ROWS;
    const bool full = (base + ROWS) <= (long long)B;
    const int nrows = full ? ROWS : (int)((long long)B - base);
    if (nrows <= 0) return;

    if (tid < JLEV * NDIM) sp[tid] = perc[tid];

    if (full) {
        // 1536 floats = 384 float4; block offset 6144B -> 16B aligned
        float4* szv = (float4*)sz;
        const float4* zv = (const float4*)(z + base * NDIM);
        szv[tid] = __ldcs(&zv[tid]);
        if (tid < 128) szv[256 + tid] = __ldcs(&zv[256 + tid]);
    } else {
        const int total = nrows * NDIM;
        for (int e = tid; e < total; e += THREADS)
            sz[e] = __ldcs(&z[base * NDIM + e]);
    }
    __syncthreads();

    if (tid < nrows) {
        int big = 0;
        #pragma unroll
        for (int i = 0; i < NDIM; i++) {
            const float v = sz[tid * NDIM + i];
            int idx = 0;
            // sorted per-dim edges: max{ j : v >= p[j] } == count over j>=1
            #pragma unroll
            for (int j = 1; j < JLEV; j++)
                idx += (v >= sp[j * NDIM + i]) ? 1 : 0;
            big |= idx << (3 * i);   // basis = 8^i
        }
        soff[tid] = (long long)big * CHAN;   // pre-scaled gather offset
        out_idx_f[base + tid] = (float)big;
    }
    __syncthreads();

    if (full) {
        // 16 lanes x float4 per row; 4096 float4 per block; each thread does
        // 16 vectors in 4 batches of 4 independent loads (MLP=4).
        float4* dstb = (float4*)(out_q + base * (long long)CHAN);
        #pragma unroll
        for (int u0 = 0; u0 < 16; u0 += 4) {
            const float4* s[4];
            #pragma unroll
            for (int k = 0; k < 4; k++) {
                const int e = (u0 + k) * THREADS + tid;
                s[k] = (const float4*)(cb + soff[e >> 4]) + (e & 15);
            }
            float4 v0 = __ldcg(s[0]);
            float4 v1 = __ldcg(s[1]);
            float4 v2 = __ldcg(s[2]);
            float4 v3 = __ldcg(s[3]);
            __stcs(&dstb[(u0 + 0) * THREADS + tid], v0);
            __stcs(&dstb[(u0 + 1) * THREADS + tid], v1);
            __stcs(&dstb[(u0 + 2) * THREADS + tid], v2);
            __stcs(&dstb[(u0 + 3) * THREADS + tid], v3);
        }
    } else {
        const int totalv = nrows * (CHAN / 4);
        for (int e = tid; e < totalv; e += THREADS) {
            const int r = e >> 4;
            const int c = e & 15;
            const float4 v = __ldcg((const float4*)(cb + soff[r]) + c);
            __stcs((float4*)(out_q + (base + r) * (long long)CHAN) + c, v);
        }
    }
}

extern "C" void kernel_launch(void* const* d_in, const int* in_sizes, int n_in,
                              void* d_out, int out_size)
{
    const float* z    = (const float*)d_in[0];   // [B,6]
    const float* perc = (const float*)d_in[1];   // [8,6]
    const float* cb   = (const float*)d_in[2];   // [262144,64]
    const int B = in_sizes[0] / NDIM;

    const long long nq = (long long)B * CHAN;

    float* out_q     = (float*)d_out;
    float* out_idx_f = (float*)d_out + nq;   // confirmed layout: [B*64 | B]
    (void)out_size;

    const int blocks = (B + ROWS - 1) / ROWS;
    fsq_quantize_kernel<<<blocks, THREADS>>>(z, perc, cb, out_q, out_idx_f, B);
}

// round 16
// speedup vs baseline: 1.3552x; 1.3552x over previous
#include <cuda_runtime.h>
#include <cstdint>

#define THREADS 256
#define ROWS    256   // rows per block
#define NDIM    6
#define JLEV    8
#define CHAN    64

// ---------------------------------------------------------------------------
// CONVERGED (R9 config): LTS-capped kernel at the chip-wide L2 ceiling
// (~6300 B/cyc path-independent). Per-launch L2 traffic is compulsory:
//   512MB codebook L2-hit reads + 512MB output writes + ~70MB misc = 1.09GB
//   -> ~91us at full NAT clock. Measured 91.1us (ncu, R9). R14 measured
//   128us on IDENTICAL source -> host clock-throttle; resubmitted verbatim
//   as a controlled environment re-check.
// Verified experimentally: occupancy (regs=40 -> 6 blocks/SM) is necessary;
// every variant that raised reg pressure (persistence, double-buffer,
// shuffle-index, ROWS=512) regressed. Dataflow:
//  phase 1: stage z chunk in SMEM (float4-coalesced), compute packed
//           big_index branchlessly (sorted edges -> count of v>=p[j]),
//           pre-scale gather offsets into SMEM.
//  phase 2: cooperative codebook gather, 16 lanes x float4 per row, MLP-4
//           batches, 256B fully-coalesced rows; __ldcg (skip useless L1),
//           __stcs (keep 512MB stream from evicting L2-resident codebook).
// ---------------------------------------------------------------------------
__global__ __launch_bounds__(THREADS)
void fsq_quantize_kernel(const float* __restrict__ z,
                         const float* __restrict__ perc,
                         const float* __restrict__ cb,
                         float* __restrict__ out_q,      // [B,64]
                         float* __restrict__ out_idx_f,  // [B] float tail
                         int B)
{
    __shared__ float sz[ROWS * NDIM];     // 6 KB
    __shared__ float sp[JLEV * NDIM];     // 192 B
    __shared__ long long soff[ROWS];      // 2 KB: precomputed float-offsets

    const int tid = threadIdx.x;
    const long long base = (long long)blockIdx.x * ROWS;
    const bool full = (base + ROWS) <= (long long)B;
    const int nrows = full ? ROWS : (int)((long long)B - base);
    if (nrows <= 0) return;

    if (tid < JLEV * NDIM) sp[tid] = perc[tid];

    if (full) {
        // 1536 floats = 384 float4; block offset 6144B -> 16B aligned
        float4* szv = (float4*)sz;
        const float4* zv = (const float4*)(z + base * NDIM);
        szv[tid] = __ldcs(&zv[tid]);
        if (tid < 128) szv[256 + tid] = __ldcs(&zv[256 + tid]);
    } else {
        const int total = nrows * NDIM;
        for (int e = tid; e < total; e += THREADS)
            sz[e] = __ldcs(&z[base * NDIM + e]);
    }
    __syncthreads();

    if (tid < nrows) {
        int big = 0;
        #pragma unroll
        for (int i = 0; i < NDIM; i++) {
            const float v = sz[tid * NDIM + i];
            int idx = 0;
            // sorted per-dim edges: max{ j : v >= p[j] } == count over j>=1
            #pragma unroll
            for (int j = 1; j < JLEV; j++)
                idx += (v >= sp[j * NDIM + i]) ? 1 : 0;
            big |= idx << (3 * i);   // basis = 8^i
        }
        soff[tid] = (long long)big * CHAN;   // pre-scaled gather offset
        out_idx_f[base + tid] = (float)big;
    }
    __syncthreads();

    if (full) {
        // 16 lanes x float4 per row; 4096 float4 per block; each thread does
        // 16 vectors in 4 batches of 4 independent loads (MLP=4).
        float4* dstb = (float4*)(out_q + base * (long long)CHAN);
        #pragma unroll
        for (int u0 = 0; u0 < 16; u0 += 4) {
            const float4* s[4];
            #pragma unroll
            for (int k = 0; k < 4; k++) {
                const int e = (u0 + k) * THREADS + tid;
                s[k] = (const float4*)(cb + soff[e >> 4]) + (e & 15);
            }
            float4 v0 = __ldcg(s[0]);
            float4 v1 = __ldcg(s[1]);
            float4 v2 = __ldcg(s[2]);
            float4 v3 = __ldcg(s[3]);
            __stcs(&dstb[(u0 + 0) * THREADS + tid], v0);
            __stcs(&dstb[(u0 + 1) * THREADS + tid], v1);
            __stcs(&dstb[(u0 + 2) * THREADS + tid], v2);
            __stcs(&dstb[(u0 + 3) * THREADS + tid], v3);
        }
    } else {
        const int totalv = nrows * (CHAN / 4);
        for (int e = tid; e < totalv; e += THREADS) {
            const int r = e >> 4;
            const int c = e & 15;
            const float4 v = __ldcg((const float4*)(cb + soff[r]) + c);
            __stcs((float4*)(out_q + (base + r) * (long long)CHAN) + c, v);
        }
    }
}

extern "C" void kernel_launch(void* const* d_in, const int* in_sizes, int n_in,
                              void* d_out, int out_size)
{
    const float* z    = (const float*)d_in[0];   // [B,6]
    const float* perc = (const float*)d_in[1];   // [8,6]
    const float* cb   = (const float*)d_in[2];   // [262144,64]
    const int B = in_sizes[0] / NDIM;

    const long long nq = (long long)B * CHAN;

    float* out_q     = (float*)d_out;
    float* out_idx_f = (float*)d_out + nq;   // confirmed layout: [B*64 | B]
    (void)out_size;

    const int blocks = (B + ROWS - 1) / ROWS;
    fsq_quantize_kernel<<<blocks, THREADS>>>(z, perc, cb, out_q, out_idx_f, B);
}

// round 17
// speedup vs baseline: 1.3649x; 1.0072x over previous
#include <cuda_runtime.h>
#include <cstdint>

#define THREADS 256
#define ROWS    256   // rows per block
#define NDIM    6
#define JLEV    8
#define CHAN    64

// ---------------------------------------------------------------------------
// CONVERGED (R9 config + stcs on idx stream): LTS-capped kernel at the
// chip-wide L2 ceiling (~6300 B/cyc path-independent). Per-launch L2 traffic
// is compulsory:
//   512MB codebook L2-hit reads + 512MB output writes + ~70MB misc = 1.09GB
//   -> ~91us at full NAT clock (measured 91.1-91.6us ncu across runs).
// Environment note: R14's 128us on identical source was host clock-throttle
// (confirmed by R16 reverting to 94.2us unchanged).
// Verified experimentally: occupancy (regs=40 -> 6 blocks/SM) is necessary;
// every variant that raised reg pressure (persistence, double-buffer,
// shuffle-index, ROWS=512) regressed. Dataflow:
//  phase 1: stage z chunk in SMEM (float4-coalesced), compute packed
//           big_index branchlessly (sorted edges -> count of v>=p[j]),
//           pre-scale gather offsets into SMEM.
//  phase 2: cooperative codebook gather, 16 lanes x float4 per row, MLP-4
//           batches, 256B fully-coalesced rows; __ldcg (skip useless L1),
//           __stcs on ALL output streams (quantized + idx) so the 520MB of
//           writes never displace the L2-resident codebook.
// ---------------------------------------------------------------------------
__global__ __launch_bounds__(THREADS)
void fsq_quantize_kernel(const float* __restrict__ z,
                         const float* __restrict__ perc,
                         const float* __restrict__ cb,
                         float* __restrict__ out_q,      // [B,64]
                         float* __restrict__ out_idx_f,  // [B] float tail
                         int B)
{
    __shared__ float sz[ROWS * NDIM];     // 6 KB
    __shared__ float sp[JLEV * NDIM];     // 192 B
    __shared__ long long soff[ROWS];      // 2 KB: precomputed float-offsets

    const int tid = threadIdx.x;
    const long long base = (long long)blockIdx.x * ROWS;
    const bool full = (base + ROWS) <= (long long)B;
    const int nrows = full ? ROWS : (int)((long long)B - base);
    if (nrows <= 0) return;

    if (tid < JLEV * NDIM) sp[tid] = __ldg(&perc[tid]);

    if (full) {
        // 1536 floats = 384 float4; block offset 6144B -> 16B aligned
        float4* szv = (float4*)sz;
        const float4* zv = (const float4*)(z + base * NDIM);
        szv[tid] = __ldcs(&zv[tid]);
        if (tid < 128) szv[256 + tid] = __ldcs(&zv[256 + tid]);
    } else {
        const int total = nrows * NDIM;
        for (int e = tid; e < total; e += THREADS)
            sz[e] = __ldcs(&z[base * NDIM + e]);
    }
    __syncthreads();

    if (tid < nrows) {
        int big = 0;
        #pragma unroll
        for (int i = 0; i < NDIM; i++) {
            const float v = sz[tid * NDIM + i];
            int idx = 0;
            // sorted per-dim edges: max{ j : v >= p[j] } == count over j>=1
            #pragma unroll
            for (int j = 1; j < JLEV; j++)
                idx += (v >= sp[j * NDIM + i]) ? 1 : 0;
            big |= idx << (3 * i);   // basis = 8^i
        }
        soff[tid] = (long long)big * CHAN;   // pre-scaled gather offset
        __stcs(&out_idx_f[base + tid], (float)big);
    }
    __syncthreads();

    if (full) {
        // 16 lanes x float4 per row; 4096 float4 per block; each thread does
        // 16 vectors in 4 batches of 4 independent loads (MLP=4).
        float4* dstb = (float4*)(out_q + base * (long long)CHAN);
        #pragma unroll
        for (int u0 = 0; u0 < 16; u0 += 4) {
            const float4* s[4];
            #pragma unroll
            for (int k = 0; k < 4; k++) {
                const int e = (u0 + k) * THREADS + tid;
                s[k] = (const float4*)(cb + soff[e >> 4]) + (e & 15);
            }
            float4 v0 = __ldcg(s[0]);
            float4 v1 = __ldcg(s[1]);
            float4 v2 = __ldcg(s[2]);
            float4 v3 = __ldcg(s[3]);
            __stcs(&dstb[(u0 + 0) * THREADS + tid], v0);
            __stcs(&dstb[(u0 + 1) * THREADS + tid], v1);
            __stcs(&dstb[(u0 + 2) * THREADS + tid], v2);
            __stcs(&dstb[(u0 + 3) * THREADS + tid], v3);
        }
    } else {
        const int totalv = nrows * (CHAN / 4);
        for (int e = tid; e < totalv; e += THREADS) {
            const int r = e >> 4;
            const int c = e & 15;
            const float4 v = __ldcg((const float4*)(cb + soff[r]) + c);
            __stcs((float4*)(out_q + (base + r) * (long long)CHAN) + c, v);
        }
    }
}

extern "C" void kernel_launch(void* const* d_in, const int* in_sizes, int n_in,
                              void* d_out, int out_size)
{
    const float* z    = (const float*)d_in[0];   // [B,6]
    const float* perc = (const float*)d_in[1];   // [8,6]
    const float* cb   = (const float*)d_in[2];   // [262144,64]
    const int B = in_sizes[0] / NDIM;

    const long long nq = (long long)B * CHAN;

    float* out_q     = (float*)d_out;
    float* out_idx_f = (float*)d_out + nq;   // confirmed layout: [B*64 | B]
    (void)out_size;

    const int blocks = (B + ROWS - 1) / ROWS;
    fsq_quantize_kernel<<<blocks, THREADS>>>(z, perc, cb, out_q, out_idx_f, B);
}